// round 8
// baseline (speedup 1.0000x reference)
#include <cuda_runtime.h>
#include <cstdint>

// out[b][o][i][l] = white_table[o][i][ x[b][i][o][l] ]
// B=8, O=I=64, L=2048. L contiguous on both sides -> fully coalesced vec4.
// Best-measured shape (R2): one block per (o,i) pair, 1KB LUT in smem, rolled
// 8-batch x 2-vec4 stream. Single change: x reads use __ldcg (no L1 alloc —
// zero-reuse stream), freeing L1tex bandwidth for the conflicted LDS lookups.

#define B_DIM 8
#define CH 64
#define L_DIM 2048
#define THREADS 256

__global__ __launch_bounds__(THREADS) void white_transpose_kernel(
    const int* __restrict__ x,
    const float* __restrict__ table,
    float* __restrict__ out)
{
    const int idx = blockIdx.x;          // 0..4095
    const int i = idx & (CH - 1);
    const int o = idx >> 6;

    __shared__ float lut[256];
    lut[threadIdx.x] = table[((o * CH + i) << 8) + threadIdx.x];
    __syncthreads();

    const size_t bstride4 = (size_t)CH * CH * (L_DIM / 4);  // int4 units per batch
    const int4* __restrict__ xin =
        reinterpret_cast<const int4*>(x) + (size_t)(i * CH + o) * (L_DIM / 4);
    float4* __restrict__ op =
        reinterpret_cast<float4*>(out) + (size_t)(o * CH + i) * (L_DIM / 4);

    #pragma unroll
    for (int b = 0; b < B_DIM; b++) {
        const size_t base = b * bstride4;
        #pragma unroll
        for (int v = 0; v < (L_DIM / 4) / THREADS; v++) {
            const int vi = v * THREADS + threadIdx.x;
            int4 xi = __ldcg(xin + base + vi);
            float4 r;
            r.x = lut[xi.x];
            r.y = lut[xi.y];
            r.z = lut[xi.z];
            r.w = lut[xi.w];
            op[base + vi] = r;
        }
    }
}

extern "C" void kernel_launch(void* const* d_in, const int* in_sizes, int n_in,
                              void* d_out, int out_size)
{
    const int* x = (const int*)d_in[0];          // [8, 64, 64, 2048] int32
    const float* table = (const float*)d_in[1];  // [64, 64, 256] float32
    float* out = (float*)d_out;                  // [8, 64, 64, 2048] float32

    const int grid = CH * CH;  // 4096 blocks, one per (o,i)
    white_transpose_kernel<<<grid, THREADS>>>(x, table, out);
}

// round 9
// speedup vs baseline: 1.0322x; 1.0322x over previous
#include <cuda_runtime.h>
#include <cstdint>

// out[b][o][i][l] = white_table[o][i][ x[b][i][o][l] ]
// B=8, O=I=64, L=2048. L contiguous on both sides -> fully coalesced vec4.
// R2 shape (one block per (o,i), rolled 8x2 vec4 stream) + 8-way replicated
// LUT in smem: lane l reads copy (l&7) at word idx*8+(l&7), cutting expected
// LDS conflict degree ~3.4 -> ~1.9 with only 8KB smem (8 blocks/SM retained).

#define B_DIM 8
#define CH 64
#define L_DIM 2048
#define THREADS 256

__global__ __launch_bounds__(THREADS) void white_transpose_kernel(
    const int* __restrict__ x,
    const float* __restrict__ table,
    float* __restrict__ out)
{
    const int idx = blockIdx.x;          // 0..4095
    const int i = idx & (CH - 1);
    const int o = idx >> 6;

    __shared__ float lut[256 * 8];       // 8 replicas, interleaved: lut[k*8 + c]
    {
        const float v = table[((o * CH + i) << 8) + threadIdx.x];
        const int base = threadIdx.x << 3;
        #pragma unroll
        for (int c = 0; c < 8; c++) lut[base + c] = v;
    }
    __syncthreads();

    const int lane_c = threadIdx.x & 7;  // this thread's replica
    const float* __restrict__ myl = lut + lane_c;

    const size_t bstride4 = (size_t)CH * CH * (L_DIM / 4);  // int4 units per batch
    const int4* __restrict__ xin =
        reinterpret_cast<const int4*>(x) + (size_t)(i * CH + o) * (L_DIM / 4);
    float4* __restrict__ op =
        reinterpret_cast<float4*>(out) + (size_t)(o * CH + i) * (L_DIM / 4);

    #pragma unroll
    for (int b = 0; b < B_DIM; b++) {
        const size_t base = b * bstride4;
        #pragma unroll
        for (int v = 0; v < (L_DIM / 4) / THREADS; v++) {
            const int vi = v * THREADS + threadIdx.x;
            int4 xi = xin[base + vi];
            float4 r;
            r.x = myl[xi.x << 3];
            r.y = myl[xi.y << 3];
            r.z = myl[xi.z << 3];
            r.w = myl[xi.w << 3];
            op[base + vi] = r;
        }
    }
}

extern "C" void kernel_launch(void* const* d_in, const int* in_sizes, int n_in,
                              void* d_out, int out_size)
{
    const int* x = (const int*)d_in[0];          // [8, 64, 64, 2048] int32
    const float* table = (const float*)d_in[1];  // [64, 64, 256] float32
    float* out = (float*)d_out;                  // [8, 64, 64, 2048] float32

    const int grid = CH * CH;  // 4096 blocks, one per (o,i)
    white_transpose_kernel<<<grid, THREADS>>>(x, table, out);
}